// round 2
// baseline (speedup 1.0000x reference)
#include <cuda_runtime.h>
#include <math.h>

// ---------------------------------------------------------------------------
// MGDT forward, fp32 baseline.
// Shapes: B=8 T=16 C=4 H=W=84 P=14 NT=36 TPS=39 L=624 D=512 NH=8 DH=64 NL=6
//         DFF=2048 NRET=120 NACT=18 NREW=3
// ---------------------------------------------------------------------------

namespace cfg {
constexpr int B = 8, T = 16, C = 4, H = 84, W = 84, P = 14;
constexpr int NT = 36, TPS = 39, L = 624;
constexpr int D = 512, NH = 8, DH = 64, NL = 6, DFF = 2048;
constexpr int NRET = 120, NACT = 18, NREW = 3;
constexpr int ROWS = B * L;            // 4992
constexpr int NPATCH = B * T * NT;     // 4608
constexpr int PDIM = C * P * P;        // 784
}

using namespace cfg;

// -------------------- scratch (device globals; no runtime alloc) -----------
__device__ float g_patches[NPATCH * PDIM];        // 3.61M
__device__ float g_x[ROWS * D];                   // residual stream
__device__ float g_xn[ROWS * D];                  // LN output
__device__ float g_qkv[ROWS * 3 * D];             // q|k|v
__device__ float g_att[B * NH * L * L];           // scores / probs (~100MB)
__device__ float g_o[ROWS * D];                   // attn out (also patch-embed out)
__device__ float g_hid[ROWS * DFF];               // ffn hidden

// -------------------- patch extraction -------------------------------------
__global__ void patchify_kernel(const float* __restrict__ frames) {
    int i = blockIdx.x * blockDim.x + threadIdx.x;
    if (i >= NPATCH * PDIM) return;
    int prow = i / PDIM, f = i - prow * PDIM;
    int bt = prow / NT, n = prow - bt * NT;
    int gy = n / 6, gx = n - gy * 6;
    int c = f / (P * P);
    int r = f - c * P * P;
    int py = r / P, px = r - py * P;
    long src = (((long)bt * C + c) * H + gy * P + py) * W + gx * P + px;
    g_patches[i] = frames[src];
}

// -------------------- generic C = A(MxK) @ W(NxK)^T + bias, w/ epilogue -----
// EPI: 0 = none, 1 = residual add (res), 2 = exact GELU
template <int EPI>
__global__ void gemm_kernel(const float* __restrict__ A, const float* __restrict__ Wm,
                            const float* __restrict__ bias, const float* __restrict__ res,
                            float* __restrict__ Cmat, int M, int N, int K) {
    __shared__ float As[16][68];
    __shared__ float Bs[16][68];
    int tid = threadIdx.x;
    int bm = blockIdx.y * 64, bn = blockIdx.x * 64;
    int lr = tid >> 2;            // 0..63  (row within tile)
    int lk = (tid & 3) * 4;       // 0,4,8,12
    int ty = tid >> 4, tx = tid & 15;
    float acc[4][4] = {};
    const float* Aptr = A + (long)(bm + lr) * K + lk;
    const float* Wptr = Wm + (long)(bn + lr) * K + lk;
    for (int k0 = 0; k0 < K; k0 += 16) {
        float4 av = *(const float4*)(Aptr + k0);
        float4 wv = *(const float4*)(Wptr + k0);
        As[lk + 0][lr] = av.x; As[lk + 1][lr] = av.y;
        As[lk + 2][lr] = av.z; As[lk + 3][lr] = av.w;
        Bs[lk + 0][lr] = wv.x; Bs[lk + 1][lr] = wv.y;
        Bs[lk + 2][lr] = wv.z; Bs[lk + 3][lr] = wv.w;
        __syncthreads();
#pragma unroll
        for (int kk = 0; kk < 16; kk++) {
            float4 a4 = *(const float4*)&As[kk][ty * 4];
            float4 b4 = *(const float4*)&Bs[kk][tx * 4];
            float ar[4] = {a4.x, a4.y, a4.z, a4.w};
            float br[4] = {b4.x, b4.y, b4.z, b4.w};
#pragma unroll
            for (int i = 0; i < 4; i++)
#pragma unroll
                for (int j = 0; j < 4; j++)
                    acc[i][j] = fmaf(ar[i], br[j], acc[i][j]);
        }
        __syncthreads();
    }
#pragma unroll
    for (int i = 0; i < 4; i++) {
        int row = bm + ty * 4 + i;
#pragma unroll
        for (int j = 0; j < 4; j++) {
            int col = bn + tx * 4 + j;
            float v = acc[i][j] + bias[col];
            if (EPI == 1) v += res[(long)row * N + col];
            if (EPI == 2) v = 0.5f * v * (1.0f + erff(v * 0.70710678118654752f));
            Cmat[(long)row * N + col] = v;
        }
    }
}

// -------------------- layernorm: out = (x-mu)/sqrt(var+eps)*s + b -----------
__global__ void ln_kernel(const float* __restrict__ s, const float* __restrict__ bta,
                          const float* __restrict__ in, float* __restrict__ out) {
    int row = blockIdx.x;
    const float* x = in + (long)row * D;
    int tid = threadIdx.x;
    float v0 = x[tid], v1 = x[tid + 256];
    __shared__ float red[256];
    red[tid] = v0 + v1;
    __syncthreads();
    for (int st = 128; st > 0; st >>= 1) {
        if (tid < st) red[tid] += red[tid + st];
        __syncthreads();
    }
    float mu = red[0] * (1.0f / 512.0f);
    __syncthreads();
    float d0 = v0 - mu, d1 = v1 - mu;
    red[tid] = d0 * d0 + d1 * d1;
    __syncthreads();
    for (int st = 128; st > 0; st >>= 1) {
        if (tid < st) red[tid] += red[tid + st];
        __syncthreads();
    }
    float rstd = rsqrtf(red[0] * (1.0f / 512.0f) + 1e-5f);
    float* o = out + (long)row * D;
    o[tid]       = d0 * rstd * s[tid]       + bta[tid];
    o[tid + 256] = d1 * rstd * s[tid + 256] + bta[tid + 256];
}

// -------------------- token assembly ----------------------------------------
__global__ void assemble_kernel(const int* __restrict__ rtg, const int* __restrict__ act,
                                const int* __restrict__ rew, const int* __restrict__ gid,
                                const float* __restrict__ ret_e, const float* __restrict__ act_e,
                                const float* __restrict__ rew_e, const float* __restrict__ game_e,
                                const float* __restrict__ pos_e, const float* __restrict__ type_e) {
    int row = blockIdx.x;          // b*L + l
    int b = row / L, l = row - b * L;
    int t = l / TPS, off = l - t * TPS;
    int tid = threadIdx.x;
    const float* src;
    int typ;
    if (off < NT)           { src = g_o + ((long)(b * T + t) * NT + off) * D; typ = 0; }
    else if (off == NT)     { src = ret_e + (long)rtg[b * T + t] * D;        typ = 1; }
    else if (off == NT + 1) { src = act_e + (long)act[b * T + t] * D;        typ = 2; }
    else                    { src = rew_e + (long)rew[b * T + t] * D;        typ = 3; }
    int g = gid[b];
    float* dst = g_x + (long)row * D;
    for (int d = tid; d < D; d += blockDim.x)
        dst[d] = src[d] + pos_e[(long)l * D + d] + type_e[(long)typ * D + d]
               + game_e[(long)g * D + d];
}

// -------------------- attention scores + mask -------------------------------
__global__ void attn_scores_kernel() {
    int bh = blockIdx.z;
    int b = bh >> 3, h = bh & 7;
    int q0 = blockIdx.y * 64, k0 = blockIdx.x * 64;
    __shared__ float Qs[64][68];   // [dh][m]
    __shared__ float Ks[64][68];   // [dh][n]
    int tid = threadIdx.x;
    const float* qbase = g_qkv + (long)b * L * (3 * D) + h * DH;
    const float* kbase = qbase + D;
#pragma unroll
    for (int r = 0; r < 4; r++) {
        int c = r * 256 + tid;
        int row = c >> 4;
        int d4 = (c & 15) * 4;
        float4 qv = make_float4(0, 0, 0, 0), kv = make_float4(0, 0, 0, 0);
        int gq = q0 + row, gk = k0 + row;
        if (gq < L) qv = *(const float4*)(qbase + (long)gq * (3 * D) + d4);
        if (gk < L) kv = *(const float4*)(kbase + (long)gk * (3 * D) + d4);
        Qs[d4 + 0][row] = qv.x; Qs[d4 + 1][row] = qv.y;
        Qs[d4 + 2][row] = qv.z; Qs[d4 + 3][row] = qv.w;
        Ks[d4 + 0][row] = kv.x; Ks[d4 + 1][row] = kv.y;
        Ks[d4 + 2][row] = kv.z; Ks[d4 + 3][row] = kv.w;
    }
    __syncthreads();
    int ty = tid >> 4, tx = tid & 15;
    float acc[4][4] = {};
#pragma unroll 16
    for (int kk = 0; kk < 64; kk++) {
        float4 a4 = *(const float4*)&Qs[kk][ty * 4];
        float4 b4 = *(const float4*)&Ks[kk][tx * 4];
        float ar[4] = {a4.x, a4.y, a4.z, a4.w};
        float br[4] = {b4.x, b4.y, b4.z, b4.w};
#pragma unroll
        for (int i = 0; i < 4; i++)
#pragma unroll
            for (int j = 0; j < 4; j++)
                acc[i][j] = fmaf(ar[i], br[j], acc[i][j]);
    }
    float* arow = g_att + (long)bh * L * L;
#pragma unroll
    for (int i = 0; i < 4; i++) {
        int q = q0 + ty * 4 + i;
        if (q >= L) continue;
        int sq = q / TPS, oq = q - sq * TPS;
#pragma unroll
        for (int j = 0; j < 4; j++) {
            int k = k0 + tx * 4 + j;
            if (k >= L) continue;
            int sk = k / TPS, ok = k - sk * TPS;
            bool allowed = (k <= q) || (sq == sk && oq < NT && ok < NT);
            arow[(long)q * L + k] = allowed ? acc[i][j] * 0.125f : -1e30f;
        }
    }
}

// -------------------- softmax over rows of g_att ----------------------------
__global__ void softmax_kernel() {
    long row = blockIdx.x;
    float* p = g_att + row * L;
    __shared__ float red[128];
    int tid = threadIdx.x;
    float m = -1e30f;
    for (int i = tid; i < L; i += 128) m = fmaxf(m, p[i]);
    red[tid] = m;
    __syncthreads();
    for (int st = 64; st > 0; st >>= 1) {
        if (tid < st) red[tid] = fmaxf(red[tid], red[tid + st]);
        __syncthreads();
    }
    m = red[0];
    __syncthreads();
    float sum = 0.0f;
    for (int i = tid; i < L; i += 128) {
        float e = __expf(p[i] - m);
        p[i] = e;
        sum += e;
    }
    red[tid] = sum;
    __syncthreads();
    for (int st = 64; st > 0; st >>= 1) {
        if (tid < st) red[tid] += red[tid + st];
        __syncthreads();
    }
    float inv = 1.0f / red[0];
    for (int i = tid; i < L; i += 128) p[i] *= inv;
}

// -------------------- O = att @ V (per b,h), merged heads -------------------
__global__ void attn_av_kernel() {
    int bh = blockIdx.y;
    int b = bh >> 3, h = bh & 7;
    int q0 = blockIdx.x * 64;
    __shared__ float As[16][68];   // [k][m]
    __shared__ float Vs[16][68];   // [k][n]
    int tid = threadIdx.x;
    int ty = tid >> 4, tx = tid & 15;
    int lr = tid >> 2, lk = (tid & 3) * 4;   // att load mapping
    int vk = tid >> 4, vn4 = (tid & 15) * 4; // v load mapping
    float acc[4][4] = {};
    const float* arow = g_att + (long)bh * L * L;
    const float* vbase = g_qkv + (long)b * L * (3 * D) + 2 * D + h * DH;
    for (int k0 = 0; k0 < L; k0 += 16) {
        float4 av = make_float4(0, 0, 0, 0);
        int gq = q0 + lr;
        if (gq < L) av = *(const float4*)(arow + (long)gq * L + k0 + lk);
        As[lk + 0][lr] = av.x; As[lk + 1][lr] = av.y;
        As[lk + 2][lr] = av.z; As[lk + 3][lr] = av.w;
        float4 vv = *(const float4*)(vbase + (long)(k0 + vk) * (3 * D) + vn4);
        *(float4*)&Vs[vk][vn4] = vv;
        __syncthreads();
#pragma unroll
        for (int kk = 0; kk < 16; kk++) {
            float4 a4 = *(const float4*)&As[kk][ty * 4];
            float4 b4 = *(const float4*)&Vs[kk][tx * 4];
            float ar[4] = {a4.x, a4.y, a4.z, a4.w};
            float br[4] = {b4.x, b4.y, b4.z, b4.w};
#pragma unroll
            for (int i = 0; i < 4; i++)
#pragma unroll
                for (int j = 0; j < 4; j++)
                    acc[i][j] = fmaf(ar[i], br[j], acc[i][j]);
        }
        __syncthreads();
    }
    float* obase = g_o + (long)b * L * D + h * DH;
#pragma unroll
    for (int i = 0; i < 4; i++) {
        int q = q0 + ty * 4 + i;
        if (q >= L) continue;
#pragma unroll
        for (int j = 0; j < 4; j++)
            obase[(long)q * D + tx * 4 + j] = acc[i][j];
    }
}

// -------------------- heads -------------------------------------------------
__global__ void heads_kernel(const float* __restrict__ rw, const float* __restrict__ rb,
                             const float* __restrict__ aw, const float* __restrict__ ab,
                             const float* __restrict__ ww, const float* __restrict__ wb,
                             float* __restrict__ out) {
    int bt = blockIdx.x;            // b*T + t
    int b = bt / T, t = bt - b * T;
    __shared__ float hsh[3][D];
    int tid = threadIdx.x;
    // rows (t*TPS + 35,36,37) are contiguous in g_x
    const float* base = g_x + ((long)b * L + (long)t * TPS + (NT - 1)) * D;
    for (int d = tid; d < 3 * D; d += blockDim.x)
        hsh[d / D][d % D] = base[d];
    __syncthreads();
    if (tid < NRET) {
        float s = rb[tid];
        for (int k = 0; k < D; k++) s = fmaf(hsh[0][k], rw[(long)tid * D + k], s);
        out[(long)bt * NRET + tid] = s;
    } else if (tid < NRET + NACT) {
        int j = tid - NRET;
        float s = ab[j];
        for (int k = 0; k < D; k++) s = fmaf(hsh[1][k], aw[(long)j * D + k], s);
        out[(long)B * T * NRET + (long)bt * NACT + j] = s;
    } else if (tid < NRET + NACT + NREW) {
        int j = tid - NRET - NACT;
        float s = wb[j];
        for (int k = 0; k < D; k++) s = fmaf(hsh[2][k], ww[(long)j * D + k], s);
        out[(long)B * T * (NRET + NACT) + (long)bt * NREW + j] = s;
    }
}

// -------------------- launch ------------------------------------------------
extern "C" void kernel_launch(void* const* d_in, const int* in_sizes, int n_in,
                              void* d_out, int out_size) {
    const float* frames   = (const float*)d_in[0];
    const int*   rtg      = (const int*)d_in[1];
    const int*   actions  = (const int*)d_in[2];
    const int*   rewards  = (const int*)d_in[3];
    const int*   gids     = (const int*)d_in[4];
    const float* patch_w  = (const float*)d_in[5];
    const float* patch_b  = (const float*)d_in[6];
    const float* ret_e    = (const float*)d_in[7];
    const float* act_e    = (const float*)d_in[8];
    const float* rew_e    = (const float*)d_in[9];
    const float* game_e   = (const float*)d_in[10];
    const float* pos_e    = (const float*)d_in[11];
    const float* type_e   = (const float*)d_in[12];
    const float* qkv_w    = (const float*)d_in[13];
    const float* qkv_b    = (const float*)d_in[14];
    const float* out_w    = (const float*)d_in[15];
    const float* out_b    = (const float*)d_in[16];
    const float* ln1_s    = (const float*)d_in[17];
    const float* ln1_b    = (const float*)d_in[18];
    const float* ln2_s    = (const float*)d_in[19];
    const float* ln2_b    = (const float*)d_in[20];
    const float* ffn_w1   = (const float*)d_in[21];
    const float* ffn_b1   = (const float*)d_in[22];
    const float* ffn_w2   = (const float*)d_in[23];
    const float* ffn_b2   = (const float*)d_in[24];
    const float* ret_hw   = (const float*)d_in[25];
    const float* ret_hb   = (const float*)d_in[26];
    const float* act_hw   = (const float*)d_in[27];
    const float* act_hb   = (const float*)d_in[28];
    const float* rew_hw   = (const float*)d_in[29];
    const float* rew_hb   = (const float*)d_in[30];

    float *p_patches, *p_x, *p_xn, *p_qkv, *p_o, *p_hid;
    cudaGetSymbolAddress((void**)&p_patches, g_patches);
    cudaGetSymbolAddress((void**)&p_x, g_x);
    cudaGetSymbolAddress((void**)&p_xn, g_xn);
    cudaGetSymbolAddress((void**)&p_qkv, g_qkv);
    cudaGetSymbolAddress((void**)&p_o, g_o);
    cudaGetSymbolAddress((void**)&p_hid, g_hid);

    // 1. patchify + patch embed (into g_o as obs buffer)
    patchify_kernel<<<(NPATCH * PDIM + 255) / 256, 256>>>(frames);
    gemm_kernel<0><<<dim3(D / 64, NPATCH / 64), 256>>>(p_patches, patch_w, patch_b,
                                                       nullptr, p_o, NPATCH, D, PDIM);
    // 2. assemble sequence with embeddings -> g_x
    assemble_kernel<<<ROWS, 256>>>(rtg, actions, rewards, gids, ret_e, act_e, rew_e,
                                   game_e, pos_e, type_e);

    // 3. transformer layers
    for (int i = 0; i < NL; i++) {
        ln_kernel<<<ROWS, 256>>>(ln1_s + (long)i * D, ln1_b + (long)i * D, p_x, p_xn);
        gemm_kernel<0><<<dim3(3 * D / 64, ROWS / 64), 256>>>(
            p_xn, qkv_w + (long)i * 3 * D * D, qkv_b + (long)i * 3 * D,
            nullptr, p_qkv, ROWS, 3 * D, D);
        attn_scores_kernel<<<dim3(10, 10, B * NH), 256>>>();
        softmax_kernel<<<B * NH * L, 128>>>();
        attn_av_kernel<<<dim3(10, B * NH), 256>>>();
        gemm_kernel<1><<<dim3(D / 64, ROWS / 64), 256>>>(
            p_o, out_w + (long)i * D * D, out_b + (long)i * D, p_x, p_x, ROWS, D, D);
        ln_kernel<<<ROWS, 256>>>(ln2_s + (long)i * D, ln2_b + (long)i * D, p_x, p_xn);
        gemm_kernel<2><<<dim3(DFF / 64, ROWS / 64), 256>>>(
            p_xn, ffn_w1 + (long)i * DFF * D, ffn_b1 + (long)i * DFF,
            nullptr, p_hid, ROWS, DFF, D);
        gemm_kernel<1><<<dim3(D / 64, ROWS / 64), 256>>>(
            p_hid, ffn_w2 + (long)i * D * DFF, ffn_b2 + (long)i * D, p_x, p_x,
            ROWS, D, DFF);
    }

    // 4. heads
    heads_kernel<<<B * T, 256>>>(ret_hw, ret_hb, act_hw, act_hb, rew_hw, rew_hb,
                                 (float*)d_out);
}

// round 4
// speedup vs baseline: 1.8874x; 1.8874x over previous
#include <cuda_runtime.h>
#include <math.h>
#include <stdint.h>

// ---------------------------------------------------------------------------
// MGDT forward. Linear layers on tf32 tensor cores (mma.sync m16n8k8),
// attention + patch embed fp32.
// Shapes: B=8 T=16 C=4 H=W=84 P=14 NT=36 TPS=39 L=624 D=512 NH=8 DH=64 NL=6
//         DFF=2048 NRET=120 NACT=18 NREW=3
// ---------------------------------------------------------------------------

namespace cfg {
constexpr int B = 8, T = 16, C = 4, H = 84, W = 84, P = 14;
constexpr int NT = 36, TPS = 39, L = 624;
constexpr int D = 512, NH = 8, DH = 64, NL = 6, DFF = 2048;
constexpr int NRET = 120, NACT = 18, NREW = 3;
constexpr int ROWS = B * L;            // 4992
constexpr int NPATCH = B * T * NT;     // 4608
constexpr int PDIM = C * P * P;        // 784
}

using namespace cfg;

// -------------------- scratch (device globals; no runtime alloc) -----------
__device__ float g_patches[NPATCH * PDIM];
__device__ float g_x[ROWS * D];
__device__ float g_xn[ROWS * D];
__device__ float g_qkv[ROWS * 3 * D];
__device__ float g_att[B * NH * L * L];
__device__ float g_o[ROWS * D];
__device__ float g_hid[ROWS * DFF];

__device__ __forceinline__ float ftf32(float x) {
    uint32_t u;
    asm("cvt.rna.tf32.f32 %0, %1;" : "=r"(u) : "f"(x));
    return __uint_as_float(u);
}

// -------------------- patch extraction -------------------------------------
__global__ void patchify_kernel(const float* __restrict__ frames) {
    int i = blockIdx.x * blockDim.x + threadIdx.x;
    if (i >= NPATCH * PDIM) return;
    int prow = i / PDIM, f = i - prow * PDIM;
    int bt = prow / NT, n = prow - bt * NT;
    int gy = n / 6, gx = n - gy * 6;
    int c = f / (P * P);
    int r = f - c * P * P;
    int py = r / P, px = r - py * P;
    long src = (((long)bt * C + c) * H + gy * P + py) * W + gx * P + px;
    g_patches[i] = frames[src];
}

// -------------------- fp32 GEMM (patch embed only) --------------------------
template <int EPI>
__global__ void gemm_kernel(const float* __restrict__ A, const float* __restrict__ Wm,
                            const float* __restrict__ bias, const float* __restrict__ res,
                            float* __restrict__ Cmat, int M, int N, int K) {
    __shared__ float As[16][68];
    __shared__ float Bs[16][68];
    int tid = threadIdx.x;
    int bm = blockIdx.y * 64, bn = blockIdx.x * 64;
    int lr = tid >> 2;
    int lk = (tid & 3) * 4;
    int ty = tid >> 4, tx = tid & 15;
    float acc[4][4] = {};
    const float* Aptr = A + (long)(bm + lr) * K + lk;
    const float* Wptr = Wm + (long)(bn + lr) * K + lk;
    for (int k0 = 0; k0 < K; k0 += 16) {
        float4 av = *(const float4*)(Aptr + k0);
        float4 wv = *(const float4*)(Wptr + k0);
        As[lk + 0][lr] = av.x; As[lk + 1][lr] = av.y;
        As[lk + 2][lr] = av.z; As[lk + 3][lr] = av.w;
        Bs[lk + 0][lr] = wv.x; Bs[lk + 1][lr] = wv.y;
        Bs[lk + 2][lr] = wv.z; Bs[lk + 3][lr] = wv.w;
        __syncthreads();
#pragma unroll
        for (int kk = 0; kk < 16; kk++) {
            float4 a4 = *(const float4*)&As[kk][ty * 4];
            float4 b4 = *(const float4*)&Bs[kk][tx * 4];
            float ar[4] = {a4.x, a4.y, a4.z, a4.w};
            float br[4] = {b4.x, b4.y, b4.z, b4.w};
#pragma unroll
            for (int i = 0; i < 4; i++)
#pragma unroll
                for (int j = 0; j < 4; j++)
                    acc[i][j] = fmaf(ar[i], br[j], acc[i][j]);
        }
        __syncthreads();
    }
#pragma unroll
    for (int i = 0; i < 4; i++) {
        int row = bm + ty * 4 + i;
#pragma unroll
        for (int j = 0; j < 4; j++) {
            int col = bn + tx * 4 + j;
            float v = acc[i][j] + bias[col];
            if (EPI == 1) v += res[(long)row * N + col];
            if (EPI == 2) v = 0.5f * v * (1.0f + erff(v * 0.70710678118654752f));
            Cmat[(long)row * N + col] = v;
        }
    }
}

// -------------------- tf32 MMA GEMM: C = A(MxK) @ W(NxK)^T + bias ----------
// Block 128x64, 8 warps (4 along M x 2 along N), warp tile 32x32, k-tile 32.
// Requires M%128==0, N%64==0, K%32==0.
// EPI: 0 none, 1 residual add, 2 exact GELU
template <int EPI>
__global__ __launch_bounds__(256) void mma_gemm_kernel(
        const float* __restrict__ A, const float* __restrict__ Wm,
        const float* __restrict__ bias, const float* __restrict__ res,
        float* __restrict__ Cmat, int M, int N, int K) {
    __shared__ float As[128][36];
    __shared__ float Bs[64][36];
    int tid = threadIdx.x;
    int bm = blockIdx.y * 128, bn = blockIdx.x * 64;
    int warp = tid >> 5, lane = tid & 31;
    int grp = lane >> 2, qd = lane & 3;
    int wm0 = (warp >> 1) * 32, wn0 = (warp & 1) * 32;
    float acc[2][4][4] = {};

    int arow = tid >> 3;             // 0..31
    int af4 = (tid & 7) * 4;         // 0..28

    for (int k0 = 0; k0 < K; k0 += 32) {
        // load A tile: 128x32
#pragma unroll
        for (int i = 0; i < 4; i++) {
            int r = arow + 32 * i;
            float4 v = *(const float4*)(A + (long)(bm + r) * K + k0 + af4);
            As[r][af4 + 0] = ftf32(v.x);
            As[r][af4 + 1] = ftf32(v.y);
            As[r][af4 + 2] = ftf32(v.z);
            As[r][af4 + 3] = ftf32(v.w);
        }
        // load B tile: 64x32  (W rows are output cols)
#pragma unroll
        for (int i = 0; i < 2; i++) {
            int idx = tid + 256 * i;
            int r = idx >> 3;
            int f4 = (idx & 7) * 4;
            float4 v = *(const float4*)(Wm + (long)(bn + r) * K + k0 + f4);
            Bs[r][f4 + 0] = ftf32(v.x);
            Bs[r][f4 + 1] = ftf32(v.y);
            Bs[r][f4 + 2] = ftf32(v.z);
            Bs[r][f4 + 3] = ftf32(v.w);
        }
        __syncthreads();
#pragma unroll
        for (int ks = 0; ks < 4; ks++) {
            uint32_t a[2][4];
            uint32_t b[4][2];
#pragma unroll
            for (int mi = 0; mi < 2; mi++) {
                int r = wm0 + mi * 16 + grp;
                int kk = ks * 8 + qd;
                a[mi][0] = __float_as_uint(As[r][kk]);
                a[mi][1] = __float_as_uint(As[r + 8][kk]);
                a[mi][2] = __float_as_uint(As[r][kk + 4]);
                a[mi][3] = __float_as_uint(As[r + 8][kk + 4]);
            }
#pragma unroll
            for (int ni = 0; ni < 4; ni++) {
                int c = wn0 + ni * 8 + grp;
                int kk = ks * 8 + qd;
                b[ni][0] = __float_as_uint(Bs[c][kk]);
                b[ni][1] = __float_as_uint(Bs[c][kk + 4]);
            }
#pragma unroll
            for (int mi = 0; mi < 2; mi++)
#pragma unroll
                for (int ni = 0; ni < 4; ni++)
                    asm volatile(
                        "mma.sync.aligned.m16n8k8.row.col.f32.tf32.tf32.f32 "
                        "{%0,%1,%2,%3},{%4,%5,%6,%7},{%8,%9},{%0,%1,%2,%3};\n"
                        : "+f"(acc[mi][ni][0]), "+f"(acc[mi][ni][1]),
                          "+f"(acc[mi][ni][2]), "+f"(acc[mi][ni][3])
                        : "r"(a[mi][0]), "r"(a[mi][1]), "r"(a[mi][2]), "r"(a[mi][3]),
                          "r"(b[ni][0]), "r"(b[ni][1]));
        }
        __syncthreads();
    }
    // epilogue: c0 (r, c), c1 (r, c+1), c2 (r+8, c), c3 (r+8, c+1)
#pragma unroll
    for (int mi = 0; mi < 2; mi++) {
#pragma unroll
        for (int ni = 0; ni < 4; ni++) {
            int r = bm + wm0 + mi * 16 + grp;
            int c = bn + wn0 + ni * 8 + 2 * qd;
            float b0 = bias[c], b1 = bias[c + 1];
#pragma unroll
            for (int h = 0; h < 2; h++) {
                int row = r + 8 * h;
                float v0 = acc[mi][ni][2 * h + 0] + b0;
                float v1 = acc[mi][ni][2 * h + 1] + b1;
                if (EPI == 1) {
                    const float2 rr = *(const float2*)(res + (long)row * N + c);
                    v0 += rr.x; v1 += rr.y;
                }
                if (EPI == 2) {
                    v0 = 0.5f * v0 * (1.0f + erff(v0 * 0.70710678118654752f));
                    v1 = 0.5f * v1 * (1.0f + erff(v1 * 0.70710678118654752f));
                }
                *(float2*)(Cmat + (long)row * N + c) = make_float2(v0, v1);
            }
        }
    }
}

// -------------------- layernorm ---------------------------------------------
__global__ void ln_kernel(const float* __restrict__ s, const float* __restrict__ bta,
                          const float* __restrict__ in, float* __restrict__ out) {
    int row = blockIdx.x;
    const float* x = in + (long)row * D;
    int tid = threadIdx.x;
    float v0 = x[tid], v1 = x[tid + 256];
    __shared__ float red[256];
    red[tid] = v0 + v1;
    __syncthreads();
    for (int st = 128; st > 0; st >>= 1) {
        if (tid < st) red[tid] += red[tid + st];
        __syncthreads();
    }
    float mu = red[0] * (1.0f / 512.0f);
    __syncthreads();
    float d0 = v0 - mu, d1 = v1 - mu;
    red[tid] = d0 * d0 + d1 * d1;
    __syncthreads();
    for (int st = 128; st > 0; st >>= 1) {
        if (tid < st) red[tid] += red[tid + st];
        __syncthreads();
    }
    float rstd = rsqrtf(red[0] * (1.0f / 512.0f) + 1e-5f);
    float* o = out + (long)row * D;
    o[tid]       = d0 * rstd * s[tid]       + bta[tid];
    o[tid + 256] = d1 * rstd * s[tid + 256] + bta[tid + 256];
}

// -------------------- token assembly ----------------------------------------
__global__ void assemble_kernel(const int* __restrict__ rtg, const int* __restrict__ act,
                                const int* __restrict__ rew, const int* __restrict__ gid,
                                const float* __restrict__ ret_e, const float* __restrict__ act_e,
                                const float* __restrict__ rew_e, const float* __restrict__ game_e,
                                const float* __restrict__ pos_e, const float* __restrict__ type_e) {
    int row = blockIdx.x;
    int b = row / L, l = row - b * L;
    int t = l / TPS, off = l - t * TPS;
    int tid = threadIdx.x;
    const float* src;
    int typ;
    if (off < NT)           { src = g_o + ((long)(b * T + t) * NT + off) * D; typ = 0; }
    else if (off == NT)     { src = ret_e + (long)rtg[b * T + t] * D;        typ = 1; }
    else if (off == NT + 1) { src = act_e + (long)act[b * T + t] * D;        typ = 2; }
    else                    { src = rew_e + (long)rew[b * T + t] * D;        typ = 3; }
    int g = gid[b];
    float* dst = g_x + (long)row * D;
    for (int d = tid; d < D; d += blockDim.x)
        dst[d] = src[d] + pos_e[(long)l * D + d] + type_e[(long)typ * D + d]
               + game_e[(long)g * D + d];
}

// -------------------- attention scores + mask -------------------------------
__global__ void attn_scores_kernel() {
    int bh = blockIdx.z;
    int b = bh >> 3, h = bh & 7;
    int q0 = blockIdx.y * 64, k0 = blockIdx.x * 64;
    __shared__ float Qs[64][68];
    __shared__ float Ks[64][68];
    int tid = threadIdx.x;
    const float* qbase = g_qkv + (long)b * L * (3 * D) + h * DH;
    const float* kbase = qbase + D;
#pragma unroll
    for (int r = 0; r < 4; r++) {
        int c = r * 256 + tid;
        int row = c >> 4;
        int d4 = (c & 15) * 4;
        float4 qv = make_float4(0, 0, 0, 0), kv = make_float4(0, 0, 0, 0);
        int gq = q0 + row, gk = k0 + row;
        if (gq < L) qv = *(const float4*)(qbase + (long)gq * (3 * D) + d4);
        if (gk < L) kv = *(const float4*)(kbase + (long)gk * (3 * D) + d4);
        Qs[d4 + 0][row] = qv.x; Qs[d4 + 1][row] = qv.y;
        Qs[d4 + 2][row] = qv.z; Qs[d4 + 3][row] = qv.w;
        Ks[d4 + 0][row] = kv.x; Ks[d4 + 1][row] = kv.y;
        Ks[d4 + 2][row] = kv.z; Ks[d4 + 3][row] = kv.w;
    }
    __syncthreads();
    int ty = tid >> 4, tx = tid & 15;
    float acc[4][4] = {};
#pragma unroll 16
    for (int kk = 0; kk < 64; kk++) {
        float4 a4 = *(const float4*)&Qs[kk][ty * 4];
        float4 b4 = *(const float4*)&Ks[kk][tx * 4];
        float ar[4] = {a4.x, a4.y, a4.z, a4.w};
        float br[4] = {b4.x, b4.y, b4.z, b4.w};
#pragma unroll
        for (int i = 0; i < 4; i++)
#pragma unroll
            for (int j = 0; j < 4; j++)
                acc[i][j] = fmaf(ar[i], br[j], acc[i][j]);
    }
    float* arow = g_att + (long)bh * L * L;
#pragma unroll
    for (int i = 0; i < 4; i++) {
        int q = q0 + ty * 4 + i;
        if (q >= L) continue;
        int sq = q / TPS, oq = q - sq * TPS;
#pragma unroll
        for (int j = 0; j < 4; j++) {
            int k = k0 + tx * 4 + j;
            if (k >= L) continue;
            int sk = k / TPS, ok = k - sk * TPS;
            bool allowed = (k <= q) || (sq == sk && oq < NT && ok < NT);
            arow[(long)q * L + k] = allowed ? acc[i][j] * 0.125f : -1e30f;
        }
    }
}

// -------------------- softmax ----------------------------------------------
__global__ void softmax_kernel() {
    long row = blockIdx.x;
    float* p = g_att + row * L;
    __shared__ float red[128];
    int tid = threadIdx.x;
    float m = -1e30f;
    for (int i = tid; i < L; i += 128) m = fmaxf(m, p[i]);
    red[tid] = m;
    __syncthreads();
    for (int st = 64; st > 0; st >>= 1) {
        if (tid < st) red[tid] = fmaxf(red[tid], red[tid + st]);
        __syncthreads();
    }
    m = red[0];
    __syncthreads();
    float sum = 0.0f;
    for (int i = tid; i < L; i += 128) {
        float e = __expf(p[i] - m);
        p[i] = e;
        sum += e;
    }
    red[tid] = sum;
    __syncthreads();
    for (int st = 64; st > 0; st >>= 1) {
        if (tid < st) red[tid] += red[tid + st];
        __syncthreads();
    }
    float inv = 1.0f / red[0];
    for (int i = tid; i < L; i += 128) p[i] *= inv;
}

// -------------------- O = att @ V -------------------------------------------
__global__ void attn_av_kernel() {
    int bh = blockIdx.y;
    int b = bh >> 3, h = bh & 7;
    int q0 = blockIdx.x * 64;
    __shared__ float As[16][68];
    __shared__ float Vs[16][68];
    int tid = threadIdx.x;
    int ty = tid >> 4, tx = tid & 15;
    int lr = tid >> 2, lk = (tid & 3) * 4;
    int vk = tid >> 4, vn4 = (tid & 15) * 4;
    float acc[4][4] = {};
    const float* arow = g_att + (long)bh * L * L;
    const float* vbase = g_qkv + (long)b * L * (3 * D) + 2 * D + h * DH;
    for (int k0 = 0; k0 < L; k0 += 16) {
        float4 av = make_float4(0, 0, 0, 0);
        int gq = q0 + lr;
        if (gq < L) av = *(const float4*)(arow + (long)gq * L + k0 + lk);
        As[lk + 0][lr] = av.x; As[lk + 1][lr] = av.y;
        As[lk + 2][lr] = av.z; As[lk + 3][lr] = av.w;
        float4 vv = *(const float4*)(vbase + (long)(k0 + vk) * (3 * D) + vn4);
        *(float4*)&Vs[vk][vn4] = vv;
        __syncthreads();
#pragma unroll
        for (int kk = 0; kk < 16; kk++) {
            float4 a4 = *(const float4*)&As[kk][ty * 4];
            float4 b4 = *(const float4*)&Vs[kk][tx * 4];
            float ar[4] = {a4.x, a4.y, a4.z, a4.w};
            float br[4] = {b4.x, b4.y, b4.z, b4.w};
#pragma unroll
            for (int i = 0; i < 4; i++)
#pragma unroll
                for (int j = 0; j < 4; j++)
                    acc[i][j] = fmaf(ar[i], br[j], acc[i][j]);
        }
        __syncthreads();
    }
    float* obase = g_o + (long)b * L * D + h * DH;
#pragma unroll
    for (int i = 0; i < 4; i++) {
        int q = q0 + ty * 4 + i;
        if (q >= L) continue;
#pragma unroll
        for (int j = 0; j < 4; j++)
            obase[(long)q * D + tx * 4 + j] = acc[i][j];
    }
}

// -------------------- heads -------------------------------------------------
__global__ void heads_kernel(const float* __restrict__ rw, const float* __restrict__ rb,
                             const float* __restrict__ aw, const float* __restrict__ ab,
                             const float* __restrict__ ww, const float* __restrict__ wb,
                             float* __restrict__ out) {
    int bt = blockIdx.x;
    int b = bt / T, t = bt - b * T;
    __shared__ float hsh[3][D];
    int tid = threadIdx.x;
    const float* base = g_x + ((long)b * L + (long)t * TPS + (NT - 1)) * D;
    for (int d = tid; d < 3 * D; d += blockDim.x)
        hsh[d / D][d % D] = base[d];
    __syncthreads();
    if (tid < NRET) {
        float s = rb[tid];
        for (int k = 0; k < D; k++) s = fmaf(hsh[0][k], rw[(long)tid * D + k], s);
        out[(long)bt * NRET + tid] = s;
    } else if (tid < NRET + NACT) {
        int j = tid - NRET;
        float s = ab[j];
        for (int k = 0; k < D; k++) s = fmaf(hsh[1][k], aw[(long)j * D + k], s);
        out[(long)B * T * NRET + (long)bt * NACT + j] = s;
    } else if (tid < NRET + NACT + NREW) {
        int j = tid - NRET - NACT;
        float s = wb[j];
        for (int k = 0; k < D; k++) s = fmaf(hsh[2][k], ww[(long)j * D + k], s);
        out[(long)B * T * (NRET + NACT) + (long)bt * NREW + j] = s;
    }
}

// -------------------- launch ------------------------------------------------
extern "C" void kernel_launch(void* const* d_in, const int* in_sizes, int n_in,
                              void* d_out, int out_size) {
    const float* frames   = (const float*)d_in[0];
    const int*   rtg      = (const int*)d_in[1];
    const int*   actions  = (const int*)d_in[2];
    const int*   rewards  = (const int*)d_in[3];
    const int*   gids     = (const int*)d_in[4];
    const float* patch_w  = (const float*)d_in[5];
    const float* patch_b  = (const float*)d_in[6];
    const float* ret_e    = (const float*)d_in[7];
    const float* act_e    = (const float*)d_in[8];
    const float* rew_e    = (const float*)d_in[9];
    const float* game_e   = (const float*)d_in[10];
    const float* pos_e    = (const float*)d_in[11];
    const float* type_e   = (const float*)d_in[12];
    const float* qkv_w    = (const float*)d_in[13];
    const float* qkv_b    = (const float*)d_in[14];
    const float* out_w    = (const float*)d_in[15];
    const float* out_b    = (const float*)d_in[16];
    const float* ln1_s    = (const float*)d_in[17];
    const float* ln1_b    = (const float*)d_in[18];
    const float* ln2_s    = (const float*)d_in[19];
    const float* ln2_b    = (const float*)d_in[20];
    const float* ffn_w1   = (const float*)d_in[21];
    const float* ffn_b1   = (const float*)d_in[22];
    const float* ffn_w2   = (const float*)d_in[23];
    const float* ffn_b2   = (const float*)d_in[24];
    const float* ret_hw   = (const float*)d_in[25];
    const float* ret_hb   = (const float*)d_in[26];
    const float* act_hw   = (const float*)d_in[27];
    const float* act_hb   = (const float*)d_in[28];
    const float* rew_hw   = (const float*)d_in[29];
    const float* rew_hb   = (const float*)d_in[30];

    float *p_patches, *p_x, *p_xn, *p_qkv, *p_o, *p_hid;
    cudaGetSymbolAddress((void**)&p_patches, g_patches);
    cudaGetSymbolAddress((void**)&p_x, g_x);
    cudaGetSymbolAddress((void**)&p_xn, g_xn);
    cudaGetSymbolAddress((void**)&p_qkv, g_qkv);
    cudaGetSymbolAddress((void**)&p_o, g_o);
    cudaGetSymbolAddress((void**)&p_hid, g_hid);

    // 1. patchify + patch embed (fp32; K=784 not divisible by 32)
    patchify_kernel<<<(NPATCH * PDIM + 255) / 256, 256>>>(frames);
    gemm_kernel<0><<<dim3(D / 64, NPATCH / 64), 256>>>(p_patches, patch_w, patch_b,
                                                       nullptr, p_o, NPATCH, D, PDIM);
    // 2. assemble sequence with embeddings -> g_x
    assemble_kernel<<<ROWS, 256>>>(rtg, actions, rewards, gids, ret_e, act_e, rew_e,
                                   game_e, pos_e, type_e);

    // 3. transformer layers
    for (int i = 0; i < NL; i++) {
        ln_kernel<<<ROWS, 256>>>(ln1_s + (long)i * D, ln1_b + (long)i * D, p_x, p_xn);
        mma_gemm_kernel<0><<<dim3(3 * D / 64, ROWS / 128), 256>>>(
            p_xn, qkv_w + (long)i * 3 * D * D, qkv_b + (long)i * 3 * D,
            nullptr, p_qkv, ROWS, 3 * D, D);
        attn_scores_kernel<<<dim3(10, 10, B * NH), 256>>>();
        softmax_kernel<<<B * NH * L, 128>>>();
        attn_av_kernel<<<dim3(10, B * NH), 256>>>();
        mma_gemm_kernel<1><<<dim3(D / 64, ROWS / 128), 256>>>(
            p_o, out_w + (long)i * D * D, out_b + (long)i * D, p_x, p_x, ROWS, D, D);
        ln_kernel<<<ROWS, 256>>>(ln2_s + (long)i * D, ln2_b + (long)i * D, p_x, p_xn);
        mma_gemm_kernel<2><<<dim3(DFF / 64, ROWS / 128), 256>>>(
            p_xn, ffn_w1 + (long)i * DFF * D, ffn_b1 + (long)i * DFF,
            nullptr, p_hid, ROWS, DFF, D);
        mma_gemm_kernel<1><<<dim3(D / 64, ROWS / 128), 256>>>(
            p_hid, ffn_w2 + (long)i * D * DFF, ffn_b2 + (long)i * D, p_x, p_x,
            ROWS, D, DFF);
    }

    // 4. heads
    heads_kernel<<<B * T, 256>>>(ret_hw, ret_hb, act_hw, act_hb, rew_hw, rew_hb,
                                 (float*)d_out);
}

// round 7
// speedup vs baseline: 2.3806x; 1.2613x over previous
#include <cuda_runtime.h>
#include <math.h>
#include <stdint.h>

// ---------------------------------------------------------------------------
// MGDT forward. Linear layers on tf32 tensor cores (mma.sync m16n8k8),
// fused fp32 flash attention (dynamic smem) exploiting prefix-structure of
// the mask, patch embed fp32.
// Shapes: B=8 T=16 C=4 H=W=84 P=14 NT=36 TPS=39 L=624 D=512 NH=8 DH=64 NL=6
//         DFF=2048 NRET=120 NACT=18 NREW=3
// ---------------------------------------------------------------------------

namespace cfg {
constexpr int B = 8, T = 16, C = 4, H = 84, W = 84, P = 14;
constexpr int NT = 36, TPS = 39, L = 624;
constexpr int D = 512, NH = 8, DH = 64, NL = 6, DFF = 2048;
constexpr int NRET = 120, NACT = 18, NREW = 3;
constexpr int ROWS = B * L;            // 4992
constexpr int NPATCH = B * T * NT;     // 4608
constexpr int PDIM = C * P * P;        // 784
}

using namespace cfg;

// -------------------- scratch (device globals; no runtime alloc) -----------
__device__ float g_patches[NPATCH * PDIM];
__device__ float g_x[ROWS * D];
__device__ float g_xn[ROWS * D];
__device__ float g_qkv[ROWS * 3 * D];
__device__ float g_o[ROWS * D];
__device__ float g_hid[ROWS * DFF];

__device__ __forceinline__ float ftf32(float x) {
    uint32_t u;
    asm("cvt.rna.tf32.f32 %0, %1;" : "=r"(u) : "f"(x));
    return __uint_as_float(u);
}

// -------------------- patch extraction -------------------------------------
__global__ void patchify_kernel(const float* __restrict__ frames) {
    int i = blockIdx.x * blockDim.x + threadIdx.x;
    if (i >= NPATCH * PDIM) return;
    int prow = i / PDIM, f = i - prow * PDIM;
    int bt = prow / NT, n = prow - bt * NT;
    int gy = n / 6, gx = n - gy * 6;
    int c = f / (P * P);
    int r = f - c * P * P;
    int py = r / P, px = r - py * P;
    long src = (((long)bt * C + c) * H + gy * P + py) * W + gx * P + px;
    g_patches[i] = frames[src];
}

// -------------------- fp32 GEMM (patch embed only) --------------------------
template <int EPI>
__global__ void gemm_kernel(const float* __restrict__ A, const float* __restrict__ Wm,
                            const float* __restrict__ bias, const float* __restrict__ res,
                            float* __restrict__ Cmat, int M, int N, int K) {
    __shared__ float As[16][68];
    __shared__ float Bs[16][68];
    int tid = threadIdx.x;
    int bm = blockIdx.y * 64, bn = blockIdx.x * 64;
    int lr = tid >> 2;
    int lk = (tid & 3) * 4;
    int ty = tid >> 4, tx = tid & 15;
    float acc[4][4] = {};
    const float* Aptr = A + (long)(bm + lr) * K + lk;
    const float* Wptr = Wm + (long)(bn + lr) * K + lk;
    for (int k0 = 0; k0 < K; k0 += 16) {
        float4 av = *(const float4*)(Aptr + k0);
        float4 wv = *(const float4*)(Wptr + k0);
        As[lk + 0][lr] = av.x; As[lk + 1][lr] = av.y;
        As[lk + 2][lr] = av.z; As[lk + 3][lr] = av.w;
        Bs[lk + 0][lr] = wv.x; Bs[lk + 1][lr] = wv.y;
        Bs[lk + 2][lr] = wv.z; Bs[lk + 3][lr] = wv.w;
        __syncthreads();
#pragma unroll
        for (int kk = 0; kk < 16; kk++) {
            float4 a4 = *(const float4*)&As[kk][ty * 4];
            float4 b4 = *(const float4*)&Bs[kk][tx * 4];
            float ar[4] = {a4.x, a4.y, a4.z, a4.w};
            float br[4] = {b4.x, b4.y, b4.z, b4.w};
#pragma unroll
            for (int i = 0; i < 4; i++)
#pragma unroll
                for (int j = 0; j < 4; j++)
                    acc[i][j] = fmaf(ar[i], br[j], acc[i][j]);
        }
        __syncthreads();
    }
#pragma unroll
    for (int i = 0; i < 4; i++) {
        int row = bm + ty * 4 + i;
#pragma unroll
        for (int j = 0; j < 4; j++) {
            int col = bn + tx * 4 + j;
            float v = acc[i][j] + bias[col];
            if (EPI == 1) v += res[(long)row * N + col];
            if (EPI == 2) v = 0.5f * v * (1.0f + erff(v * 0.70710678118654752f));
            Cmat[(long)row * N + col] = v;
        }
    }
}

// -------------------- tf32 MMA GEMM: C = A(MxK) @ W(NxK)^T + bias ----------
// Block 128x64, 8 warps (4 along M x 2 along N), warp tile 32x32, k-tile 32.
// EPI: 0 none, 1 residual add, 2 exact GELU
template <int EPI>
__global__ __launch_bounds__(256) void mma_gemm_kernel(
        const float* __restrict__ A, const float* __restrict__ Wm,
        const float* __restrict__ bias, const float* __restrict__ res,
        float* __restrict__ Cmat, int M, int N, int K) {
    __shared__ float As[128][36];
    __shared__ float Bs[64][36];
    int tid = threadIdx.x;
    int bm = blockIdx.y * 128, bn = blockIdx.x * 64;
    int warp = tid >> 5, lane = tid & 31;
    int grp = lane >> 2, qd = lane & 3;
    int wm0 = (warp >> 1) * 32, wn0 = (warp & 1) * 32;
    float acc[2][4][4] = {};

    int arow = tid >> 3;             // 0..31
    int af4 = (tid & 7) * 4;         // 0..28

    for (int k0 = 0; k0 < K; k0 += 32) {
#pragma unroll
        for (int i = 0; i < 4; i++) {
            int r = arow + 32 * i;
            float4 v = *(const float4*)(A + (long)(bm + r) * K + k0 + af4);
            As[r][af4 + 0] = ftf32(v.x);
            As[r][af4 + 1] = ftf32(v.y);
            As[r][af4 + 2] = ftf32(v.z);
            As[r][af4 + 3] = ftf32(v.w);
        }
#pragma unroll
        for (int i = 0; i < 2; i++) {
            int idx = tid + 256 * i;
            int r = idx >> 3;
            int f4 = (idx & 7) * 4;
            float4 v = *(const float4*)(Wm + (long)(bn + r) * K + k0 + f4);
            Bs[r][f4 + 0] = ftf32(v.x);
            Bs[r][f4 + 1] = ftf32(v.y);
            Bs[r][f4 + 2] = ftf32(v.z);
            Bs[r][f4 + 3] = ftf32(v.w);
        }
        __syncthreads();
#pragma unroll
        for (int ks = 0; ks < 4; ks++) {
            uint32_t a[2][4];
            uint32_t b[4][2];
#pragma unroll
            for (int mi = 0; mi < 2; mi++) {
                int r = wm0 + mi * 16 + grp;
                int kk = ks * 8 + qd;
                a[mi][0] = __float_as_uint(As[r][kk]);
                a[mi][1] = __float_as_uint(As[r + 8][kk]);
                a[mi][2] = __float_as_uint(As[r][kk + 4]);
                a[mi][3] = __float_as_uint(As[r + 8][kk + 4]);
            }
#pragma unroll
            for (int ni = 0; ni < 4; ni++) {
                int c = wn0 + ni * 8 + grp;
                int kk = ks * 8 + qd;
                b[ni][0] = __float_as_uint(Bs[c][kk]);
                b[ni][1] = __float_as_uint(Bs[c][kk + 4]);
            }
#pragma unroll
            for (int mi = 0; mi < 2; mi++)
#pragma unroll
                for (int ni = 0; ni < 4; ni++)
                    asm volatile(
                        "mma.sync.aligned.m16n8k8.row.col.f32.tf32.tf32.f32 "
                        "{%0,%1,%2,%3},{%4,%5,%6,%7},{%8,%9},{%0,%1,%2,%3};\n"
                        : "+f"(acc[mi][ni][0]), "+f"(acc[mi][ni][1]),
                          "+f"(acc[mi][ni][2]), "+f"(acc[mi][ni][3])
                        : "r"(a[mi][0]), "r"(a[mi][1]), "r"(a[mi][2]), "r"(a[mi][3]),
                          "r"(b[ni][0]), "r"(b[ni][1]));
        }
        __syncthreads();
    }
#pragma unroll
    for (int mi = 0; mi < 2; mi++) {
#pragma unroll
        for (int ni = 0; ni < 4; ni++) {
            int r = bm + wm0 + mi * 16 + grp;
            int c = bn + wn0 + ni * 8 + 2 * qd;
            float b0 = bias[c], b1 = bias[c + 1];
#pragma unroll
            for (int h = 0; h < 2; h++) {
                int row = r + 8 * h;
                float v0 = acc[mi][ni][2 * h + 0] + b0;
                float v1 = acc[mi][ni][2 * h + 1] + b1;
                if (EPI == 1) {
                    const float2 rr = *(const float2*)(res + (long)row * N + c);
                    v0 += rr.x; v1 += rr.y;
                }
                if (EPI == 2) {
                    v0 = 0.5f * v0 * (1.0f + erff(v0 * 0.70710678118654752f));
                    v1 = 0.5f * v1 * (1.0f + erff(v1 * 0.70710678118654752f));
                }
                *(float2*)(Cmat + (long)row * N + c) = make_float2(v0, v1);
            }
        }
    }
}

// -------------------- layernorm ---------------------------------------------
__global__ void ln_kernel(const float* __restrict__ s, const float* __restrict__ bta,
                          const float* __restrict__ in, float* __restrict__ out) {
    int row = blockIdx.x;
    const float* x = in + (long)row * D;
    int tid = threadIdx.x;
    float v0 = x[tid], v1 = x[tid + 256];
    __shared__ float red[256];
    red[tid] = v0 + v1;
    __syncthreads();
    for (int st = 128; st > 0; st >>= 1) {
        if (tid < st) red[tid] += red[tid + st];
        __syncthreads();
    }
    float mu = red[0] * (1.0f / 512.0f);
    __syncthreads();
    float d0 = v0 - mu, d1 = v1 - mu;
    red[tid] = d0 * d0 + d1 * d1;
    __syncthreads();
    for (int st = 128; st > 0; st >>= 1) {
        if (tid < st) red[tid] += red[tid + st];
        __syncthreads();
    }
    float rstd = rsqrtf(red[0] * (1.0f / 512.0f) + 1e-5f);
    float* o = out + (long)row * D;
    o[tid]       = d0 * rstd * s[tid]       + bta[tid];
    o[tid + 256] = d1 * rstd * s[tid + 256] + bta[tid + 256];
}

// -------------------- token assembly ----------------------------------------
__global__ void assemble_kernel(const int* __restrict__ rtg, const int* __restrict__ act,
                                const int* __restrict__ rew, const int* __restrict__ gid,
                                const float* __restrict__ ret_e, const float* __restrict__ act_e,
                                const float* __restrict__ rew_e, const float* __restrict__ game_e,
                                const float* __restrict__ pos_e, const float* __restrict__ type_e) {
    int row = blockIdx.x;
    int b = row / L, l = row - b * L;
    int t = l / TPS, off = l - t * TPS;
    int tid = threadIdx.x;
    const float* src;
    int typ;
    if (off < NT)           { src = g_o + ((long)(b * T + t) * NT + off) * D; typ = 0; }
    else if (off == NT)     { src = ret_e + (long)rtg[b * T + t] * D;        typ = 1; }
    else if (off == NT + 1) { src = act_e + (long)act[b * T + t] * D;        typ = 2; }
    else                    { src = rew_e + (long)rew[b * T + t] * D;        typ = 3; }
    int g = gid[b];
    float* dst = g_x + (long)row * D;
    for (int d = tid; d < D; d += blockDim.x)
        dst[d] = src[d] + pos_e[(long)l * D + d] + type_e[(long)typ * D + d]
               + game_e[(long)g * D + d];
}

// -------------------- fused flash attention (fp32, dynamic smem) ------------
// Mask is a per-row PREFIX: allowed(q,k) <=> k <= klim(q), where
// klim(q) = step_start + NT-1 for obs tokens (covers same-step obs run),
//           q otherwise (pure causal). klim is monotone in q, so each q-tile
// only iterates k-tiles 0..klim_max/64 (~36% fewer tiles than full LxL).
// Block: 64 q-rows x (full DH=64), 256 threads, 4x4 micro-tile per thread.
// Dynamic smem: 4 tiles of [64][68] fp32 = 69632 B (> 48KB static limit).
constexpr int FA_TILE_FLOATS = 64 * 68;
constexpr int FA_SMEM_BYTES = 4 * FA_TILE_FLOATS * 4;

__global__ __launch_bounds__(256) void flash_attn_kernel() {
    extern __shared__ float fa_smem[];
    float (*Qs)[68] = (float(*)[68])(fa_smem);                      // [d][q]
    float (*Ks)[68] = (float(*)[68])(fa_smem + FA_TILE_FLOATS);     // [d][k]
    float (*Vs)[68] = (float(*)[68])(fa_smem + 2 * FA_TILE_FLOATS); // [k][d]
    float (*Ps)[68] = (float(*)[68])(fa_smem + 3 * FA_TILE_FLOATS); // [k][q]
    int bh = blockIdx.y;
    int b = bh >> 3, h = bh & 7;
    int q0 = blockIdx.x * 64;
    int tid = threadIdx.x;
    int ty = tid >> 4, tx = tid & 15;
    const float* qbase = g_qkv + (long)b * L * (3 * D) + h * DH;
    const float* kbase = qbase + D;
    const float* vbase = qbase + 2 * D;

    // load Q tile [d][q]
#pragma unroll
    for (int r = 0; r < 4; r++) {
        int c = r * 256 + tid;
        int row = c >> 4;
        int d4 = (c & 15) * 4;
        float4 qv = make_float4(0, 0, 0, 0);
        int gq = q0 + row;
        if (gq < L) qv = *(const float4*)(qbase + (long)gq * (3 * D) + d4);
        Qs[d4 + 0][row] = qv.x; Qs[d4 + 1][row] = qv.y;
        Qs[d4 + 2][row] = qv.z; Qs[d4 + 3][row] = qv.w;
    }

    float m[4], l[4], acc[4][4];
#pragma unroll
    for (int i = 0; i < 4; i++) {
        m[i] = -1e30f; l[i] = 0.0f;
#pragma unroll
        for (int j = 0; j < 4; j++) acc[i][j] = 0.0f;
    }

    int klim[4];
#pragma unroll
    for (int i = 0; i < 4; i++) {
        int q = q0 + ty * 4 + i;
        if (q >= L) klim[i] = 0;
        else {
            int st = q / TPS, off = q - st * TPS;
            klim[i] = (off < NT) ? st * TPS + NT - 1 : q;
        }
    }
    int qlast = min(q0 + 63, L - 1);
    int stl = qlast / TPS, offl = qlast - stl * TPS;
    int klim_max = (offl < NT) ? stl * TPS + NT - 1 : qlast;
    int nkt = klim_max / 64 + 1;

    for (int kt = 0; kt < nkt; kt++) {
        int k0 = kt * 64;
        // load K tile [d][k] and V tile [k][d]
#pragma unroll
        for (int r = 0; r < 4; r++) {
            int c = r * 256 + tid;
            int row = c >> 4;
            int d4 = (c & 15) * 4;
            int gk = k0 + row;
            float4 kv = make_float4(0, 0, 0, 0), vv = make_float4(0, 0, 0, 0);
            if (gk < L) {
                kv = *(const float4*)(kbase + (long)gk * (3 * D) + d4);
                vv = *(const float4*)(vbase + (long)gk * (3 * D) + d4);
            }
            Ks[d4 + 0][row] = kv.x; Ks[d4 + 1][row] = kv.y;
            Ks[d4 + 2][row] = kv.z; Ks[d4 + 3][row] = kv.w;
            *(float4*)&Vs[row][d4] = vv;
        }
        __syncthreads();

        // S = Q @ K^T (4x4 per thread)
        float s[4][4] = {};
#pragma unroll 8
        for (int d = 0; d < 64; d++) {
            float4 a4 = *(const float4*)&Qs[d][ty * 4];
            float4 b4 = *(const float4*)&Ks[d][tx * 4];
            float ar[4] = {a4.x, a4.y, a4.z, a4.w};
            float br[4] = {b4.x, b4.y, b4.z, b4.w};
#pragma unroll
            for (int i = 0; i < 4; i++)
#pragma unroll
                for (int j = 0; j < 4; j++)
                    s[i][j] = fmaf(ar[i], br[j], s[i][j]);
        }

        // mask + online softmax (row reductions across the 16 tx lanes)
#pragma unroll
        for (int i = 0; i < 4; i++) {
            float rm = -1e30f;
#pragma unroll
            for (int j = 0; j < 4; j++) {
                int k = k0 + tx * 4 + j;
                s[i][j] = (k <= klim[i]) ? s[i][j] * 0.125f : -1e30f;
                rm = fmaxf(rm, s[i][j]);
            }
#pragma unroll
            for (int w = 1; w < 16; w <<= 1)
                rm = fmaxf(rm, __shfl_xor_sync(0xffffffffu, rm, w));
            float mn = fmaxf(m[i], rm);
            float corr = __expf(m[i] - mn);
            float rs = 0.0f;
#pragma unroll
            for (int j = 0; j < 4; j++) {
                float p = __expf(s[i][j] - mn);
                s[i][j] = p;
                rs += p;
            }
#pragma unroll
            for (int w = 1; w < 16; w <<= 1)
                rs += __shfl_xor_sync(0xffffffffu, rs, w);
            l[i] = l[i] * corr + rs;
            m[i] = mn;
#pragma unroll
            for (int j = 0; j < 4; j++) acc[i][j] *= corr;
        }

        // transpose P into smem: Ps[k][q], vectorized along q
        __syncthreads();
#pragma unroll
        for (int j = 0; j < 4; j++) {
            float4 pv = make_float4(s[0][j], s[1][j], s[2][j], s[3][j]);
            *(float4*)&Ps[tx * 4 + j][ty * 4] = pv;
        }
        __syncthreads();

        // acc += P @ V
#pragma unroll 8
        for (int k = 0; k < 64; k++) {
            float4 a4 = *(const float4*)&Ps[k][ty * 4];
            float4 b4 = *(const float4*)&Vs[k][tx * 4];
            float ar[4] = {a4.x, a4.y, a4.z, a4.w};
            float br[4] = {b4.x, b4.y, b4.z, b4.w};
#pragma unroll
            for (int i = 0; i < 4; i++)
#pragma unroll
                for (int j = 0; j < 4; j++)
                    acc[i][j] = fmaf(ar[i], br[j], acc[i][j]);
        }
        __syncthreads();
    }

    // epilogue: O = acc / l
    float* obase = g_o + (long)b * L * D + h * DH;
#pragma unroll
    for (int i = 0; i < 4; i++) {
        int q = q0 + ty * 4 + i;
        if (q >= L) continue;
        float inv = 1.0f / l[i];
        float4 o4 = make_float4(acc[i][0] * inv, acc[i][1] * inv,
                                acc[i][2] * inv, acc[i][3] * inv);
        *(float4*)(obase + (long)q * D + tx * 4) = o4;
    }
}

// -------------------- heads -------------------------------------------------
__global__ void heads_kernel(const float* __restrict__ rw, const float* __restrict__ rb,
                             const float* __restrict__ aw, const float* __restrict__ ab,
                             const float* __restrict__ ww, const float* __restrict__ wb,
                             float* __restrict__ out) {
    int bt = blockIdx.x;
    int b = bt / T, t = bt - b * T;
    __shared__ float hsh[3][D];
    int tid = threadIdx.x;
    const float* base = g_x + ((long)b * L + (long)t * TPS + (NT - 1)) * D;
    for (int d = tid; d < 3 * D; d += blockDim.x)
        hsh[d / D][d % D] = base[d];
    __syncthreads();
    if (tid < NRET) {
        float s = rb[tid];
        for (int k = 0; k < D; k++) s = fmaf(hsh[0][k], rw[(long)tid * D + k], s);
        out[(long)bt * NRET + tid] = s;
    } else if (tid < NRET + NACT) {
        int j = tid - NRET;
        float s = ab[j];
        for (int k = 0; k < D; k++) s = fmaf(hsh[1][k], aw[(long)j * D + k], s);
        out[(long)B * T * NRET + (long)bt * NACT + j] = s;
    } else if (tid < NRET + NACT + NREW) {
        int j = tid - NRET - NACT;
        float s = wb[j];
        for (int k = 0; k < D; k++) s = fmaf(hsh[2][k], ww[(long)j * D + k], s);
        out[(long)B * T * (NRET + NACT) + (long)bt * NREW + j] = s;
    }
}

// -------------------- launch ------------------------------------------------
extern "C" void kernel_launch(void* const* d_in, const int* in_sizes, int n_in,
                              void* d_out, int out_size) {
    const float* frames   = (const float*)d_in[0];
    const int*   rtg      = (const int*)d_in[1];
    const int*   actions  = (const int*)d_in[2];
    const int*   rewards  = (const int*)d_in[3];
    const int*   gids     = (const int*)d_in[4];
    const float* patch_w  = (const float*)d_in[5];
    const float* patch_b  = (const float*)d_in[6];
    const float* ret_e    = (const float*)d_in[7];
    const float* act_e    = (const float*)d_in[8];
    const float* rew_e    = (const float*)d_in[9];
    const float* game_e   = (const float*)d_in[10];
    const float* pos_e    = (const float*)d_in[11];
    const float* type_e   = (const float*)d_in[12];
    const float* qkv_w    = (const float*)d_in[13];
    const float* qkv_b    = (const float*)d_in[14];
    const float* out_w    = (const float*)d_in[15];
    const float* out_b    = (const float*)d_in[16];
    const float* ln1_s    = (const float*)d_in[17];
    const float* ln1_b    = (const float*)d_in[18];
    const float* ln2_s    = (const float*)d_in[19];
    const float* ln2_b    = (const float*)d_in[20];
    const float* ffn_w1   = (const float*)d_in[21];
    const float* ffn_b1   = (const float*)d_in[22];
    const float* ffn_w2   = (const float*)d_in[23];
    const float* ffn_b2   = (const float*)d_in[24];
    const float* ret_hw   = (const float*)d_in[25];
    const float* ret_hb   = (const float*)d_in[26];
    const float* act_hw   = (const float*)d_in[27];
    const float* act_hb   = (const float*)d_in[28];
    const float* rew_hw   = (const float*)d_in[29];
    const float* rew_hb   = (const float*)d_in[30];

    float *p_patches, *p_x, *p_xn, *p_qkv, *p_o, *p_hid;
    cudaGetSymbolAddress((void**)&p_patches, g_patches);
    cudaGetSymbolAddress((void**)&p_x, g_x);
    cudaGetSymbolAddress((void**)&p_xn, g_xn);
    cudaGetSymbolAddress((void**)&p_qkv, g_qkv);
    cudaGetSymbolAddress((void**)&p_o, g_o);
    cudaGetSymbolAddress((void**)&p_hid, g_hid);

    // Allow >48KB dynamic smem for the flash kernel (host-side attr set;
    // graph-capture safe, idempotent).
    cudaFuncSetAttribute(flash_attn_kernel,
                         cudaFuncAttributeMaxDynamicSharedMemorySize,
                         FA_SMEM_BYTES);

    // 1. patchify + patch embed (fp32; K=784 not divisible by 32)
    patchify_kernel<<<(NPATCH * PDIM + 255) / 256, 256>>>(frames);
    gemm_kernel<0><<<dim3(D / 64, NPATCH / 64), 256>>>(p_patches, patch_w, patch_b,
                                                       nullptr, p_o, NPATCH, D, PDIM);
    // 2. assemble sequence with embeddings -> g_x
    assemble_kernel<<<ROWS, 256>>>(rtg, actions, rewards, gids, ret_e, act_e, rew_e,
                                   game_e, pos_e, type_e);

    // 3. transformer layers
    for (int i = 0; i < NL; i++) {
        ln_kernel<<<ROWS, 256>>>(ln1_s + (long)i * D, ln1_b + (long)i * D, p_x, p_xn);
        mma_gemm_kernel<0><<<dim3(3 * D / 64, ROWS / 128), 256>>>(
            p_xn, qkv_w + (long)i * 3 * D * D, qkv_b + (long)i * 3 * D,
            nullptr, p_qkv, ROWS, 3 * D, D);
        flash_attn_kernel<<<dim3(10, B * NH), 256, FA_SMEM_BYTES>>>();
        mma_gemm_kernel<1><<<dim3(D / 64, ROWS / 128), 256>>>(
            p_o, out_w + (long)i * D * D, out_b + (long)i * D, p_x, p_x, ROWS, D, D);
        ln_kernel<<<ROWS, 256>>>(ln2_s + (long)i * D, ln2_b + (long)i * D, p_x, p_xn);
        mma_gemm_kernel<2><<<dim3(DFF / 64, ROWS / 128), 256>>>(
            p_xn, ffn_w1 + (long)i * DFF * D, ffn_b1 + (long)i * DFF,
            nullptr, p_hid, ROWS, DFF, D);
        mma_gemm_kernel<1><<<dim3(D / 64, ROWS / 128), 256>>>(
            p_hid, ffn_w2 + (long)i * D * DFF, ffn_b2 + (long)i * D, p_x, p_x,
            ROWS, D, DFF);
    }

    // 4. heads
    heads_kernel<<<B * T, 256>>>(ret_hw, ret_hb, act_hw, act_hb, rew_hw, rew_hb,
                                 (float*)d_out);
}